// round 11
// baseline (speedup 1.0000x reference)
#include <cuda_runtime.h>
#include <math.h>

// Problem constants (fixed by setup_inputs)
#define NPTS  4096
#define BB    4
#define NPER  1024
#define LL    16
#define FV    256
#define FLANG 768
#define FF    128
#define KNN   16

// ---------------- scratch (device globals; no allocations allowed) -----------
__device__ __align__(16) float g_feats[NPTS * FF];   // encoded point features
__device__ __align__(16) float g_hl[BB * LL * FF];   // lang hidden pre-BN
__device__ __align__(16) float g_lang[BB * LL * FF]; // encoded lang features
__device__ __align__(16) float g_atten[NPTS * LL];   // per-point/token logits
__device__ int   g_knn[NPTS * KNN];                  // neighbor ids (global)
__device__ int   g_c1, g_c2;                         // inter-block barrier counters

// ---------------- packed f32x2 helpers (sm_103a FFMA2 pipe) ------------------
typedef unsigned long long ull;
__device__ __forceinline__ ull pk2(float x, float y) {
    ull r; asm("mov.b64 %0, {%1, %2};" : "=l"(r) : "f"(x), "f"(y)); return r;
}
__device__ __forceinline__ ull fma2(ull a, ull b, ull c) {
    ull d; asm("fma.rn.f32x2 %0, %1, %2, %3;" : "=l"(d) : "l"(a), "l"(b), "l"(c));
    return d;
}
__device__ __forceinline__ float2 upk(ull a) {
    float2 f; asm("mov.b64 {%0, %1}, %2;" : "=f"(f.x), "=f"(f.y) : "l"(a)); return f;
}

// ---------------- MEGA kernel: lang | feat+atten | kNN -----------------------
// bids [0,64):    lang pipeline (2 phases, inter-block barrier on g_c1/g_c2)
// bids [64,192):  32 points each, block-tiled feat GEMMs + atten epilogue
// bids [192,704): 8 kNN queries each, warp per query, register top-16
#define OFF_XT 0        // [32][36]  (feat stage A, X^T chunk)
#define OFF_W  1152     // [32][128] (feat stage A/C, W chunk)
#define OFF_HT 5248     // [128][36] (feat stage B/C, H^T)
#define OFF_O  0        // [32][132] (feat stage D, O)         -- overlays XT+W
#define OFF_LG 5248     // [16][128] (feat stage D, lang tile) -- overlays HT
#define SBUF   9856

__global__ __launch_bounds__(256) void k_mega(
    const float* __restrict__ xyz, const float* __restrict__ X,
    const float* __restrict__ W1, const float* __restrict__ b1,
    const float* __restrict__ lng, const float* __restrict__ lnb,
    const float* __restrict__ W2, const float* __restrict__ b2,
    const float* __restrict__ LFT, const float* __restrict__ Wl1,
    const float* __restrict__ bl1, const float* __restrict__ bng,
    const float* __restrict__ bnb, const float* __restrict__ Wl2,
    const float* __restrict__ bl2)
{
    __shared__ __align__(16) float s[SBUF];
    int bid = blockIdx.x, tid = threadIdx.x, lane = tid & 31, warp = tid >> 5;

    if (bid < 64) {
        // ========================= LANG pipeline ===========================
        int r = bid;
        float* s_in = s;                            // 768 floats (also s_h)
        float4* s_part = (float4*)(s + 768);        // [8][32] float4

        // phase 1: hl = LFT @ Wl1 + bl1 (8-way v-split, 256 threads)
        for (int t = tid; t < FLANG; t += 256) s_in[t] = LFT[r * FLANG + t];
        __syncthreads();
        int fq = tid & 31, vs = tid >> 5;
        float4 acc = make_float4(0.f, 0.f, 0.f, 0.f);
        const float4* sv = (const float4*)(s_in + vs * 96);   // 24 float4
        int vbase = vs * 96;
        #pragma unroll 4
        for (int v4 = 0; v4 < 24; v4++) {
            float4 x = sv[v4];
            float4 w0 = ((const float4*)(Wl1 + (vbase + v4 * 4 + 0) * FF))[fq];
            float4 w1 = ((const float4*)(Wl1 + (vbase + v4 * 4 + 1) * FF))[fq];
            float4 w2 = ((const float4*)(Wl1 + (vbase + v4 * 4 + 2) * FF))[fq];
            float4 w3 = ((const float4*)(Wl1 + (vbase + v4 * 4 + 3) * FF))[fq];
            acc.x = fmaf(x.x, w0.x, acc.x); acc.y = fmaf(x.x, w0.y, acc.y);
            acc.z = fmaf(x.x, w0.z, acc.z); acc.w = fmaf(x.x, w0.w, acc.w);
            acc.x = fmaf(x.y, w1.x, acc.x); acc.y = fmaf(x.y, w1.y, acc.y);
            acc.z = fmaf(x.y, w1.z, acc.z); acc.w = fmaf(x.y, w1.w, acc.w);
            acc.x = fmaf(x.z, w2.x, acc.x); acc.y = fmaf(x.z, w2.y, acc.y);
            acc.z = fmaf(x.z, w2.z, acc.z); acc.w = fmaf(x.z, w2.w, acc.w);
            acc.x = fmaf(x.w, w3.x, acc.x); acc.y = fmaf(x.w, w3.y, acc.y);
            acc.z = fmaf(x.w, w3.z, acc.z); acc.w = fmaf(x.w, w3.w, acc.w);
        }
        s_part[vs * 32 + fq] = acc;
        __syncthreads();
        if (tid < 32) {
            float4 o = ((const float4*)bl1)[tid];
            #pragma unroll
            for (int p = 0; p < 8; p++) {
                float4 a = s_part[p * 32 + tid];
                o.x += a.x; o.y += a.y; o.z += a.z; o.w += a.w;
            }
            ((float4*)(g_hl + r * FF))[tid] = o;
            __threadfence();
        }
        __syncthreads();
        if (tid == 0) {
            atomicAdd(&g_c1, 1);
            while (atomicAdd(&g_c1, 0) < 64) __nanosleep(64);
        }
        __syncthreads();
        __threadfence();

        // phase 2: BN (global stats, recomputed redundantly) + ReLU
        if (tid < FF) {
            int f = tid;
            float m = 0.f;
            #pragma unroll 8
            for (int rr = 0; rr < 64; rr++) m += g_hl[rr * FF + f];
            m *= (1.f / 64.f);
            float v = 0.f;
            #pragma unroll 8
            for (int rr = 0; rr < 64; rr++) { float d = g_hl[rr * FF + f] - m; v = fmaf(d, d, v); }
            v *= (1.f / 64.f);
            float h = (g_hl[r * FF + f] - m) * rsqrtf(v + 1e-5f) * bng[f] + bnb[f];
            s_in[f] = fmaxf(h, 0.f);
        }
        __syncthreads();

        // phase 3: lang = relu(h) @ Wl2 + bl2 (8-way c-split)
        float4 acc2 = make_float4(0.f, 0.f, 0.f, 0.f);
        #pragma unroll 8
        for (int c = vs * 16; c < vs * 16 + 16; c++) {
            float x = s_in[c];
            float4 w = ((const float4*)(Wl2 + c * FF))[fq];
            acc2.x = fmaf(x, w.x, acc2.x); acc2.y = fmaf(x, w.y, acc2.y);
            acc2.z = fmaf(x, w.z, acc2.z); acc2.w = fmaf(x, w.w, acc2.w);
        }
        s_part[vs * 32 + fq] = acc2;
        __syncthreads();
        if (tid < 32) {
            float4 o = ((const float4*)bl2)[tid];
            #pragma unroll
            for (int p = 0; p < 8; p++) {
                float4 a = s_part[p * 32 + tid];
                o.x += a.x; o.y += a.y; o.z += a.z; o.w += a.w;
            }
            ((float4*)(g_lang + r * FF))[tid] = o;
            __threadfence();
        }
        __syncthreads();
        if (tid == 0) atomicAdd(&g_c2, 1);

    } else if (bid < 192) {
        // ================= tiled feat encoder + attention ==================
        int p0 = (bid - 64) * 32;
        int pg = tid & 7, fg = tid >> 3;   // 8 point-groups x 32 f-groups
        int p_ld = tid >> 3, kq_ld = (tid & 7) * 4;

        // ---- GEMM1: H = X @ W1 + b1 (packed f32x2, prefetched staging) ----
        float4 bv = ((const float4*)b1)[fg];
        ull accL[4], accH[4];
        #pragma unroll
        for (int i = 0; i < 4; i++) { accL[i] = pk2(bv.x, bv.y); accH[i] = pk2(bv.z, bv.w); }

        // prologue prefetch (chunk 0)
        float4 xreg = *(const float4*)&X[(p0 + p_ld) * FV + kq_ld];
        float4 wr0 = ((const float4*)W1)[0 * 256 + tid];
        float4 wr1 = ((const float4*)W1)[1 * 256 + tid];
        float4 wr2 = ((const float4*)W1)[2 * 256 + tid];
        float4 wr3 = ((const float4*)W1)[3 * 256 + tid];

        for (int kc = 0; kc < 8; kc++) {
            // commit staged chunk
            s[OFF_XT + (kq_ld + 0) * 36 + p_ld] = xreg.x;
            s[OFF_XT + (kq_ld + 1) * 36 + p_ld] = xreg.y;
            s[OFF_XT + (kq_ld + 2) * 36 + p_ld] = xreg.z;
            s[OFF_XT + (kq_ld + 3) * 36 + p_ld] = xreg.w;
            {
                float4* ws = (float4*)(s + OFF_W);
                ws[0 * 256 + tid] = wr0; ws[1 * 256 + tid] = wr1;
                ws[2 * 256 + tid] = wr2; ws[3 * 256 + tid] = wr3;
            }
            __syncthreads();
            if (kc < 7) {   // prefetch next chunk while computing
                int k0n = (kc + 1) * 32;
                xreg = *(const float4*)&X[(p0 + p_ld) * FV + k0n + kq_ld];
                const float4* wg = (const float4*)(W1 + k0n * FF);
                wr0 = wg[0 * 256 + tid]; wr1 = wg[1 * 256 + tid];
                wr2 = wg[2 * 256 + tid]; wr3 = wg[3 * 256 + tid];
            }
            #pragma unroll 8
            for (int kk = 0; kk < 32; kk++) {
                float4 xv = *(const float4*)&s[OFF_XT + kk * 36 + pg * 4];
                ulonglong2 wv = *(const ulonglong2*)&s[OFF_W + kk * FF + fg * 4];
                ull a0 = pk2(xv.x, xv.x), a1 = pk2(xv.y, xv.y);
                ull a2 = pk2(xv.z, xv.z), a3 = pk2(xv.w, xv.w);
                accL[0] = fma2(a0, wv.x, accL[0]); accH[0] = fma2(a0, wv.y, accH[0]);
                accL[1] = fma2(a1, wv.x, accL[1]); accH[1] = fma2(a1, wv.y, accH[1]);
                accL[2] = fma2(a2, wv.x, accL[2]); accH[2] = fma2(a2, wv.y, accH[2]);
                accL[3] = fma2(a3, wv.x, accL[3]); accH[3] = fma2(a3, wv.y, accH[3]);
            }
            __syncthreads();
        }
        // write H^T: sHT[f][p]
        #pragma unroll
        for (int i = 0; i < 4; i++) {
            float2 lo = upk(accL[i]), hi = upk(accH[i]);
            int p = pg * 4 + i;
            s[OFF_HT + (fg * 4 + 0) * 36 + p] = lo.x;
            s[OFF_HT + (fg * 4 + 1) * 36 + p] = lo.y;
            s[OFF_HT + (fg * 4 + 2) * 36 + p] = hi.x;
            s[OFF_HT + (fg * 4 + 3) * 36 + p] = hi.y;
        }
        __syncthreads();

        // ---- LayerNorm + ReLU, in place on sHT (warp handles 4 points) ----
        {
            float g0 = lng[lane], g1 = lng[lane + 32], g2 = lng[lane + 64], g3 = lng[lane + 96];
            float c0 = lnb[lane], c1 = lnb[lane + 32], c2 = lnb[lane + 64], c3 = lnb[lane + 96];
            #pragma unroll
            for (int pp = 0; pp < 4; pp++) {
                int p = warp * 4 + pp;
                float v0 = s[OFF_HT + lane * 36 + p];
                float v1 = s[OFF_HT + (lane + 32) * 36 + p];
                float v2 = s[OFF_HT + (lane + 64) * 36 + p];
                float v3 = s[OFF_HT + (lane + 96) * 36 + p];
                float sm = v0 + v1 + v2 + v3;
                #pragma unroll
                for (int o = 16; o; o >>= 1) sm += __shfl_xor_sync(~0u, sm, o);
                float mean = sm * (1.f / FF);
                float d0 = v0 - mean, d1 = v1 - mean, d2 = v2 - mean, d3 = v3 - mean;
                float q = d0 * d0 + d1 * d1 + d2 * d2 + d3 * d3;
                #pragma unroll
                for (int o = 16; o; o >>= 1) q += __shfl_xor_sync(~0u, q, o);
                float inv = rsqrtf(q * (1.f / FF) + 1e-5f);
                s[OFF_HT + lane * 36 + p]        = fmaxf(fmaf(d0 * inv, g0, c0), 0.f);
                s[OFF_HT + (lane + 32) * 36 + p] = fmaxf(fmaf(d1 * inv, g1, c1), 0.f);
                s[OFF_HT + (lane + 64) * 36 + p] = fmaxf(fmaf(d2 * inv, g2, c2), 0.f);
                s[OFF_HT + (lane + 96) * 36 + p] = fmaxf(fmaf(d3 * inv, g3, c3), 0.f);
            }
        }

        // ---- GEMM2: O = relu(H) @ W2 + b2 (prefetched staging) ----
        float4 b2v = ((const float4*)b2)[fg];
        ull oL[4], oH[4];
        #pragma unroll
        for (int i = 0; i < 4; i++) { oL[i] = pk2(b2v.x, b2v.y); oH[i] = pk2(b2v.z, b2v.w); }
        wr0 = ((const float4*)W2)[0 * 256 + tid];
        wr1 = ((const float4*)W2)[1 * 256 + tid];
        wr2 = ((const float4*)W2)[2 * 256 + tid];
        wr3 = ((const float4*)W2)[3 * 256 + tid];
        for (int kc = 0; kc < 4; kc++) {
            int k0 = kc * 32;
            {
                float4* ws = (float4*)(s + OFF_W);
                ws[0 * 256 + tid] = wr0; ws[1 * 256 + tid] = wr1;
                ws[2 * 256 + tid] = wr2; ws[3 * 256 + tid] = wr3;
            }
            __syncthreads();
            if (kc < 3) {
                const float4* wg = (const float4*)(W2 + (k0 + 32) * FF);
                wr0 = wg[0 * 256 + tid]; wr1 = wg[1 * 256 + tid];
                wr2 = wg[2 * 256 + tid]; wr3 = wg[3 * 256 + tid];
            }
            #pragma unroll 8
            for (int kk = 0; kk < 32; kk++) {
                float4 xv = *(const float4*)&s[OFF_HT + (k0 + kk) * 36 + pg * 4];
                ulonglong2 wv = *(const ulonglong2*)&s[OFF_W + kk * FF + fg * 4];
                ull a0 = pk2(xv.x, xv.x), a1 = pk2(xv.y, xv.y);
                ull a2 = pk2(xv.z, xv.z), a3 = pk2(xv.w, xv.w);
                oL[0] = fma2(a0, wv.x, oL[0]); oH[0] = fma2(a0, wv.y, oH[0]);
                oL[1] = fma2(a1, wv.x, oL[1]); oH[1] = fma2(a1, wv.y, oH[1]);
                oL[2] = fma2(a2, wv.x, oL[2]); oH[2] = fma2(a2, wv.y, oH[2]);
                oL[3] = fma2(a3, wv.x, oL[3]); oH[3] = fma2(a3, wv.y, oH[3]);
            }
            __syncthreads();
        }

        // ---- epilogue: store g_feats + O tile, wait for lang, atten -------
        int b = p0 >> 10;
        #pragma unroll
        for (int i = 0; i < 4; i++) {
            float2 lo = upk(oL[i]), hi = upk(oH[i]);
            float4 ov = make_float4(lo.x, lo.y, hi.x, hi.y);
            int p = pg * 4 + i;
            ((float4*)&g_feats[(p0 + p) * FF])[fg] = ov;
            *(float4*)&s[OFF_O + p * 132 + fg * 4] = ov;
        }
        if (tid == 0) { while (atomicAdd(&g_c2, 0) < 64) __nanosleep(64); }
        __syncthreads();
        __threadfence();
        {   // stage lang[b]: 2048 floats
            const float4* lg = (const float4*)(g_lang + b * LL * FF);
            float4* ls = (float4*)(s + OFF_LG);
            ls[tid] = lg[tid];
            ls[tid + 256] = lg[tid + 256];
        }
        __syncthreads();
        #pragma unroll
        for (int pp = 0; pp < 4; pp++) {
            int p = warp * 4 + pp;
            float4 ov = *(const float4*)&s[OFF_O + p * 132 + lane * 4];
            #pragma unroll
            for (int l = 0; l < LL; l++) {
                float4 lv = *(const float4*)&s[OFF_LG + l * FF + lane * 4];
                float d = ov.x * lv.x + ov.y * lv.y + ov.z * lv.z + ov.w * lv.w;
                #pragma unroll
                for (int o = 16; o; o >>= 1) d += __shfl_xor_sync(~0u, d, o);
                if (lane == 0) g_atten[(p0 + p) * LL + l] = d;
            }
        }
    } else {
        // ======================= batched kNN ===============================
        int kb = bid - 192;               // 0..511
        int bq = kb >> 7;                 // batch (128 blocks per batch)
        int lq = (kb & 127) * 8 + warp;   // local query id
        int q  = bq * NPER + lq;          // global query id

        float4* s_p = (float4*)s;         // [1024] packed xyz
        for (int t = tid; t < NPER; t += 256) {
            int g = (bq * NPER + t) * 3;
            s_p[t] = make_float4(xyz[g], xyz[g + 1], xyz[g + 2], 0.f);
        }
        __syncthreads();

        float4 qp = s_p[lq];
        float d[32];
        #pragma unroll
        for (int m = 0; m < 32; m++) {
            float4 p = s_p[m * 32 + lane];   // conflict-free, index-ordered
            float dx = qp.x - p.x, dy = qp.y - p.y, dz = qp.z - p.z;
            d[m] = fmaf(dx, dx, fmaf(dy, dy, dz * dz));
        }

        unsigned sel = 0u;
        for (int r = 0; r < KNN; r++) {
            float mv = 3.4e38f; int mm = 0;
            #pragma unroll
            for (int m = 0; m < 32; m++) {
                bool ok = !((sel >> m) & 1u) && (d[m] < mv);
                if (ok) { mv = d[m]; mm = m; }
            }
            int gi = mm * 32 + lane;
            #pragma unroll
            for (int o = 16; o; o >>= 1) {
                float ov = __shfl_xor_sync(0xffffffffu, mv, o);
                int   oi = __shfl_xor_sync(0xffffffffu, gi, o);
                if (ov < mv || (ov == mv && oi < gi)) { mv = ov; gi = oi; }
            }
            if ((gi & 31) == lane) sel |= 1u << (gi >> 5);
            if (lane == 0) g_knn[q * KNN + r] = bq * NPER + gi;
        }
    }
}

// ---------------- kernel 4: edges, warp-specialized prep + (4j x 4f) GEMMs ---
__global__ __launch_bounds__(FF) void k_edge(
    const float* __restrict__ xyz,
    const float* __restrict__ mask,
    const float* __restrict__ Wr1, const float* __restrict__ br1,
    const float* __restrict__ Wr2, const float* __restrict__ br2,
    float* __restrict__ out)
{
    int i = blockIdx.x, tid = threadIdx.x, lane = tid & 31, warp = tid >> 5;
    __shared__ int s_nb[KNN];
    __shared__ __align__(16) float s_aT[LL][16];     // [l][j] attention
    __shared__ __align__(16) float s_hidT[64][20];   // [h][j] rel hidden (pad 20)
    __shared__ __align__(16) float s_geo[KNN][12];   // geo, float4-padded rows

    if (tid < KNN) s_nb[tid] = g_knn[i * KNN + tid];
    if (i == 0 && tid == 96) { g_c1 = 0; g_c2 = 0; }   // reset barrier counters for next replay
    __syncthreads();

    if (warp == 0) {
        // ---- softmax + mask + renorm, fully in registers (8 vals/lane) ----
        // lane holds (j = lane&15, l = cb..cb+7) where cb = (lane>>4)*8
        int j = lane & 15;
        int cb = (lane >> 4) * 8;
        const float* ap = g_atten + s_nb[j] * LL + cb;
        float4 v0 = *(const float4*)ap;
        float4 v1 = *(const float4*)(ap + 4);
        float a[8] = {v0.x, v0.y, v0.z, v0.w, v1.x, v1.y, v1.z, v1.w};

        float mx[8];
        #pragma unroll
        for (int t = 0; t < 8; t++) mx[t] = a[t];
        #pragma unroll
        for (int o = 1; o <= 8; o <<= 1) {
            #pragma unroll
            for (int t = 0; t < 8; t++) mx[t] = fmaxf(mx[t], __shfl_xor_sync(~0u, mx[t], o));
        }
        float e[8], sm[8];
        #pragma unroll
        for (int t = 0; t < 8; t++) { e[t] = __expf(a[t] - mx[t]); sm[t] = e[t]; }
        #pragma unroll
        for (int o = 1; o <= 8; o <<= 1) {
            #pragma unroll
            for (int t = 0; t < 8; t++) sm[t] += __shfl_xor_sync(~0u, sm[t], o);
        }
        const float4* mp = (const float4*)(mask + i * LL + cb);
        float4 m0 = mp[0], m1 = mp[1];
        float mk[8] = {m0.x, m0.y, m0.z, m0.w, m1.x, m1.y, m1.z, m1.w};
        #pragma unroll
        for (int t = 0; t < 8; t++) a[t] = e[t] * __fdividef(mk[t], sm[t]);
        // renorm over l: lane has 8 l's; partner (xor 16) has the other 8 for same j
        float ps = 0.f;
        #pragma unroll
        for (int t = 0; t < 8; t++) ps += a[t];
        float tot = ps + __shfl_xor_sync(~0u, ps, 16);
        float inv = __fdividef(1.f, tot + 1e-7f);
        #pragma unroll
        for (int t = 0; t < 8; t++) s_aT[cb + t][j] = a[t] * inv;

    } else if (warp <= 2) {
        // ---- geo (warp 1 lanes 0-15), then hidden MLP on warps 1-2 --------
        if (warp == 1 && lane < KNN) {
            int j = lane, nj = s_nb[j];
            float xi0 = xyz[i * 3], xi1 = xyz[i * 3 + 1], xi2 = xyz[i * 3 + 2];
            float xj0 = xyz[nj * 3], xj1 = xyz[nj * 3 + 1], xj2 = xyz[nj * 3 + 2];
            float d0 = xi0 - xj0, d1 = xi1 - xj1, d2 = xi2 - xj2;
            float nr = sqrtf(d0 * d0 + d1 * d1 + d2 * d2 + 1e-12f);
            s_geo[j][0] = xi0; s_geo[j][1] = xi1; s_geo[j][2] = xi2;
            s_geo[j][3] = xj0; s_geo[j][4] = xj1; s_geo[j][5] = xj2;
            s_geo[j][6] = d0;  s_geo[j][7] = d1;  s_geo[j][8] = d2;
            s_geo[j][9] = nr;  s_geo[j][10] = 0.f; s_geo[j][11] = 0.f;
        }
        asm volatile("bar.sync 1, 64;" ::: "memory");   // warps 1+2 only

        // hidden: t2 in [0,64): h-pair hp = t2&31, j-octet jq = t2>>5
        int t2 = tid - 32;
        int hp = t2 & 31, jq = t2 >> 5;
        ull wv[10];
        #pragma unroll
        for (int dd = 0; dd < 10; dd++) wv[dd] = *(const ull*)&Wr1[dd * 64 + hp * 2];
        float2 bb = *(const float2*)&br1[hp * 2];
        ull bpk = pk2(bb.x, bb.y);
        float r0[8], r1[8];
        #pragma unroll
        for (int jj = 0; jj < 8; jj++) {
            int j = jq * 8 + jj;
            float4 ga = *(const float4*)&s_geo[j][0];
            float4 gb = *(const float4*)&s_geo[j][4];
            float2 gc = *(const float2*)&s_geo[j][8];
            ull a = bpk;
            a = fma2(pk2(ga.x, ga.x), wv[0], a);
            a = fma2(pk2(ga.y, ga.y), wv[1], a);
            a = fma2(pk2(ga.z, ga.z), wv[2], a);
            a = fma2(pk2(ga.w, ga.w), wv[3], a);
            a = fma2(pk2(gb.x, gb.x), wv[4], a);
            a = fma2(pk2(gb.y, gb.y), wv[5], a);
            a = fma2(pk2(gb.z, gb.z), wv[6], a);
            a = fma2(pk2(gb.w, gb.w), wv[7], a);
            a = fma2(pk2(gc.x, gc.x), wv[8], a);
            a = fma2(pk2(gc.y, gc.y), wv[9], a);
            float2 f2 = upk(a);
            r0[jj] = fmaxf(f2.x, 0.f);
            r1[jj] = fmaxf(f2.y, 0.f);
        }
        *(float4*)&s_hidT[hp * 2][jq * 8]         = make_float4(r0[0], r0[1], r0[2], r0[3]);
        *(float4*)&s_hidT[hp * 2][jq * 8 + 4]     = make_float4(r0[4], r0[5], r0[6], r0[7]);
        *(float4*)&s_hidT[hp * 2 + 1][jq * 8]     = make_float4(r1[0], r1[1], r1[2], r1[3]);
        *(float4*)&s_hidT[hp * 2 + 1][jq * 8 + 4] = make_float4(r1[4], r1[5], r1[6], r1[7]);
    }
    // warp 3: nothing to prep
    __syncthreads();

    int jg = tid & 3, fg = tid >> 2;    // 4 j-groups x 32 f-groups

    // ew[4j][4f] = hid @ Wr2 + br2  (packed f32x2)
    float4 b2v = ((const float4*)br2)[fg];
    ull ewL[4], ewH[4];
    #pragma unroll
    for (int jj = 0; jj < 4; jj++) { ewL[jj] = pk2(b2v.x, b2v.y); ewH[jj] = pk2(b2v.z, b2v.w); }
    #pragma unroll 8
    for (int k = 0; k < 64; k++) {
        float4 hv = *(const float4*)&s_hidT[k][jg * 4];
        ulonglong2 wv = *(const ulonglong2*)&Wr2[k * FF + fg * 4];
        ull a0 = pk2(hv.x, hv.x), a1 = pk2(hv.y, hv.y);
        ull a2 = pk2(hv.z, hv.z), a3 = pk2(hv.w, hv.w);
        ewL[0] = fma2(a0, wv.x, ewL[0]); ewH[0] = fma2(a0, wv.y, ewH[0]);
        ewL[1] = fma2(a1, wv.x, ewL[1]); ewH[1] = fma2(a1, wv.y, ewH[1]);
        ewL[2] = fma2(a2, wv.x, ewL[2]); ewH[2] = fma2(a2, wv.y, ewH[2]);
        ewL[3] = fma2(a3, wv.x, ewL[3]); ewH[3] = fma2(a3, wv.y, ewH[3]);
    }

    // ctx[4j][4f] = att @ lang_b  (packed f32x2)
    ull cxL[4] = {0ull, 0ull, 0ull, 0ull}, cxH[4] = {0ull, 0ull, 0ull, 0ull};
    const float* lb = g_lang + (i >> 10) * LL * FF;
    #pragma unroll
    for (int l = 0; l < LL; l++) {
        float4 av = *(const float4*)&s_aT[l][jg * 4];
        ulonglong2 lv = *(const ulonglong2*)&lb[l * FF + fg * 4];
        ull a0 = pk2(av.x, av.x), a1 = pk2(av.y, av.y);
        ull a2 = pk2(av.z, av.z), a3 = pk2(av.w, av.w);
        cxL[0] = fma2(a0, lv.x, cxL[0]); cxH[0] = fma2(a0, lv.y, cxH[0]);
        cxL[1] = fma2(a1, lv.x, cxL[1]); cxH[1] = fma2(a1, lv.y, cxH[1]);
        cxL[2] = fma2(a2, lv.x, cxL[2]); cxH[2] = fma2(a2, lv.y, cxH[2]);
        cxL[3] = fma2(a3, lv.x, cxL[3]); cxH[3] = fma2(a3, lv.y, cxH[3]);
    }

    // msg = feats[col] * ctx * ew, partial-sum over this thread's 4 j
    float4 res = make_float4(0.f, 0.f, 0.f, 0.f);
    #pragma unroll
    for (int jj = 0; jj < 4; jj++) {
        int nj = s_nb[jg * 4 + jj];
        float4 fv = ((const float4*)&g_feats[nj * FF])[fg];
        float2 eL = upk(ewL[jj]), eH = upk(ewH[jj]);
        float2 cL = upk(cxL[jj]), cH = upk(cxH[jj]);
        res.x = fmaf(fv.x * cL.x, eL.x, res.x);
        res.y = fmaf(fv.y * cL.y, eL.y, res.y);
        res.z = fmaf(fv.z * cH.x, eH.x, res.z);
        res.w = fmaf(fv.w * cH.y, eH.y, res.w);
    }
    // reduce the 4 jg-threads sharing this f-quad (xor 1, 2 within 4-group)
    #pragma unroll
    for (int o = 1; o <= 2; o <<= 1) {
        res.x += __shfl_xor_sync(~0u, res.x, o);
        res.y += __shfl_xor_sync(~0u, res.y, o);
        res.z += __shfl_xor_sync(~0u, res.z, o);
        res.w += __shfl_xor_sync(~0u, res.w, o);
    }
    if (jg == 0) {
        float4 rv = ((const float4*)&g_feats[i * FF])[fg];
        res.x += rv.x; res.y += rv.y; res.z += rv.z; res.w += rv.w;
        ((float4*)&out[i * FF])[fg] = res;
    }
}

// ---------------- launch ------------------------------------------------------
extern "C" void kernel_launch(void* const* d_in, const int* in_sizes, int n_in,
                              void* d_out, int out_size)
{
    const float* xyz   = (const float*)d_in[0];
    const float* feats = (const float*)d_in[2];
    const float* lft   = (const float*)d_in[3];
    const float* mask  = (const float*)d_in[4];
    const float* W1    = (const float*)d_in[5];
    const float* b1    = (const float*)d_in[6];
    const float* lng   = (const float*)d_in[7];
    const float* lnb   = (const float*)d_in[8];
    const float* W2    = (const float*)d_in[9];
    const float* b2    = (const float*)d_in[10];
    const float* Wl1   = (const float*)d_in[11];
    const float* bl1   = (const float*)d_in[12];
    const float* bng   = (const float*)d_in[13];
    const float* bnb   = (const float*)d_in[14];
    const float* Wl2   = (const float*)d_in[15];
    const float* bl2   = (const float*)d_in[16];
    const float* Wr1   = (const float*)d_in[17];
    const float* br1   = (const float*)d_in[18];
    const float* Wr2   = (const float*)d_in[19];
    const float* br2   = (const float*)d_in[20];
    float* out = (float*)d_out;

    k_mega<<<704, 256>>>(xyz, feats, W1, b1, lng, lnb, W2, b2,
                         lft, Wl1, bl1, bng, bnb, Wl2, bl2);
    k_edge<<<NPTS, FF>>>(xyz, mask, Wr1, br1, Wr2, br2, out);
}

// round 12
// speedup vs baseline: 1.5177x; 1.5177x over previous
#include <cuda_runtime.h>
#include <math.h>

// Problem constants (fixed by setup_inputs)
#define NPTS  4096
#define BB    4
#define NPER  1024
#define LL    16
#define FV    256
#define FLANG 768
#define FF    128
#define KNN   16

// ---------------- scratch (device globals; no allocations allowed) -----------
__device__ __align__(16) float g_feats[NPTS * FF];   // encoded point features
__device__ __align__(16) float g_hl[BB * LL * FF];   // lang hidden pre-BN
__device__ __align__(16) float g_lang[BB * LL * FF]; // encoded lang features
__device__ __align__(16) float g_atten[NPTS * LL];   // per-point/token logits
__device__ int   g_knn[NPTS * KNN];                  // neighbor ids (global)
__device__ int   g_c1, g_c2;                         // inter-block barrier counters

// ---------------- packed f32x2 helpers (sm_103a FFMA2 pipe) ------------------
typedef unsigned long long ull;
__device__ __forceinline__ ull pk2(float x, float y) {
    ull r; asm("mov.b64 %0, {%1, %2};" : "=l"(r) : "f"(x), "f"(y)); return r;
}
__device__ __forceinline__ ull fma2(ull a, ull b, ull c) {
    ull d; asm("fma.rn.f32x2 %0, %1, %2, %3;" : "=l"(d) : "l"(a), "l"(b), "l"(c));
    return d;
}
__device__ __forceinline__ float2 upk(ull a) {
    float2 f; asm("mov.b64 {%0, %1}, %2;" : "=f"(f.x), "=f"(f.y) : "l"(a)); return f;
}

// ---------------- MEGA kernel: lang | feat+atten | kNN -----------------------
// bids [0,64):    lang pipeline (2 phases, inter-block barrier on g_c1/g_c2)
// bids [64,192):  32 points each, block-tiled feat GEMMs + atten epilogue
// bids [192,704): 8 kNN queries each, warp per query, register top-16
#define OFF_XT 0        // [32][36]  (feat stage A, X^T chunk)
#define OFF_W  1152     // [32][128] (feat stage A/C, W chunk)
#define OFF_HT 5248     // [128][36] (feat stage B/C, H^T)
#define OFF_O  0        // [32][132] (feat stage D, O)         -- overlays XT+W
#define OFF_LG 5248     // [16][128] (feat stage D, lang tile) -- overlays HT
#define SBUF   9856

__global__ __launch_bounds__(256) void k_mega(
    const float* __restrict__ xyz, const float* __restrict__ X,
    const float* __restrict__ W1, const float* __restrict__ b1,
    const float* __restrict__ lng, const float* __restrict__ lnb,
    const float* __restrict__ W2, const float* __restrict__ b2,
    const float* __restrict__ LFT, const float* __restrict__ Wl1,
    const float* __restrict__ bl1, const float* __restrict__ bng,
    const float* __restrict__ bnb, const float* __restrict__ Wl2,
    const float* __restrict__ bl2)
{
    __shared__ __align__(16) float s[SBUF];
    int bid = blockIdx.x, tid = threadIdx.x, lane = tid & 31, warp = tid >> 5;

    if (bid < 64) {
        // ========================= LANG pipeline ===========================
        int r = bid;
        float* s_in = s;                            // 768 floats (also s_h)
        float4* s_part = (float4*)(s + 768);        // [8][32] float4

        // phase 1: hl = LFT @ Wl1 + bl1 (8-way v-split, 256 threads)
        for (int t = tid; t < FLANG; t += 256) s_in[t] = LFT[r * FLANG + t];
        __syncthreads();
        int fq = tid & 31, vs = tid >> 5;
        float4 acc = make_float4(0.f, 0.f, 0.f, 0.f);
        const float4* sv = (const float4*)(s_in + vs * 96);   // 24 float4
        int vbase = vs * 96;
        #pragma unroll 4
        for (int v4 = 0; v4 < 24; v4++) {
            float4 x = sv[v4];
            float4 w0 = ((const float4*)(Wl1 + (vbase + v4 * 4 + 0) * FF))[fq];
            float4 w1 = ((const float4*)(Wl1 + (vbase + v4 * 4 + 1) * FF))[fq];
            float4 w2 = ((const float4*)(Wl1 + (vbase + v4 * 4 + 2) * FF))[fq];
            float4 w3 = ((const float4*)(Wl1 + (vbase + v4 * 4 + 3) * FF))[fq];
            acc.x = fmaf(x.x, w0.x, acc.x); acc.y = fmaf(x.x, w0.y, acc.y);
            acc.z = fmaf(x.x, w0.z, acc.z); acc.w = fmaf(x.x, w0.w, acc.w);
            acc.x = fmaf(x.y, w1.x, acc.x); acc.y = fmaf(x.y, w1.y, acc.y);
            acc.z = fmaf(x.y, w1.z, acc.z); acc.w = fmaf(x.y, w1.w, acc.w);
            acc.x = fmaf(x.z, w2.x, acc.x); acc.y = fmaf(x.z, w2.y, acc.y);
            acc.z = fmaf(x.z, w2.z, acc.z); acc.w = fmaf(x.z, w2.w, acc.w);
            acc.x = fmaf(x.w, w3.x, acc.x); acc.y = fmaf(x.w, w3.y, acc.y);
            acc.z = fmaf(x.w, w3.z, acc.z); acc.w = fmaf(x.w, w3.w, acc.w);
        }
        s_part[vs * 32 + fq] = acc;
        __syncthreads();
        if (tid < 32) {
            float4 o = ((const float4*)bl1)[tid];
            #pragma unroll
            for (int p = 0; p < 8; p++) {
                float4 a = s_part[p * 32 + tid];
                o.x += a.x; o.y += a.y; o.z += a.z; o.w += a.w;
            }
            ((float4*)(g_hl + r * FF))[tid] = o;
            __threadfence();
        }
        __syncthreads();
        if (tid == 0) {
            atomicAdd(&g_c1, 1);
            while (atomicAdd(&g_c1, 0) < 64) __nanosleep(64);
        }
        __syncthreads();
        __threadfence();

        // phase 2: BN (global stats, recomputed redundantly) + ReLU
        if (tid < FF) {
            int f = tid;
            float m = 0.f;
            #pragma unroll 8
            for (int rr = 0; rr < 64; rr++) m += g_hl[rr * FF + f];
            m *= (1.f / 64.f);
            float v = 0.f;
            #pragma unroll 8
            for (int rr = 0; rr < 64; rr++) { float d = g_hl[rr * FF + f] - m; v = fmaf(d, d, v); }
            v *= (1.f / 64.f);
            float h = (g_hl[r * FF + f] - m) * rsqrtf(v + 1e-5f) * bng[f] + bnb[f];
            s_in[f] = fmaxf(h, 0.f);
        }
        __syncthreads();

        // phase 3: lang = relu(h) @ Wl2 + bl2 (8-way c-split)
        float4 acc2 = make_float4(0.f, 0.f, 0.f, 0.f);
        #pragma unroll 8
        for (int c = vs * 16; c < vs * 16 + 16; c++) {
            float x = s_in[c];
            float4 w = ((const float4*)(Wl2 + c * FF))[fq];
            acc2.x = fmaf(x, w.x, acc2.x); acc2.y = fmaf(x, w.y, acc2.y);
            acc2.z = fmaf(x, w.z, acc2.z); acc2.w = fmaf(x, w.w, acc2.w);
        }
        s_part[vs * 32 + fq] = acc2;
        __syncthreads();
        if (tid < 32) {
            float4 o = ((const float4*)bl2)[tid];
            #pragma unroll
            for (int p = 0; p < 8; p++) {
                float4 a = s_part[p * 32 + tid];
                o.x += a.x; o.y += a.y; o.z += a.z; o.w += a.w;
            }
            ((float4*)(g_lang + r * FF))[tid] = o;
            __threadfence();
        }
        __syncthreads();
        if (tid == 0) atomicAdd(&g_c2, 1);

    } else if (bid < 192) {
        // ================= tiled feat encoder + attention ==================
        int p0 = (bid - 64) * 32;
        int pg = tid & 7, fg = tid >> 3;   // 8 point-groups x 32 f-groups
        int p_ld = tid >> 3, kq_ld = (tid & 7) * 4;

        // ---- GEMM1: H = X @ W1 + b1 (packed f32x2, prefetched staging) ----
        float4 bv = ((const float4*)b1)[fg];
        ull accL[4], accH[4];
        #pragma unroll
        for (int i = 0; i < 4; i++) { accL[i] = pk2(bv.x, bv.y); accH[i] = pk2(bv.z, bv.w); }

        // prologue prefetch (chunk 0)
        float4 xreg = *(const float4*)&X[(p0 + p_ld) * FV + kq_ld];
        float4 wr0 = ((const float4*)W1)[0 * 256 + tid];
        float4 wr1 = ((const float4*)W1)[1 * 256 + tid];
        float4 wr2 = ((const float4*)W1)[2 * 256 + tid];
        float4 wr3 = ((const float4*)W1)[3 * 256 + tid];

        for (int kc = 0; kc < 8; kc++) {
            // commit staged chunk
            s[OFF_XT + (kq_ld + 0) * 36 + p_ld] = xreg.x;
            s[OFF_XT + (kq_ld + 1) * 36 + p_ld] = xreg.y;
            s[OFF_XT + (kq_ld + 2) * 36 + p_ld] = xreg.z;
            s[OFF_XT + (kq_ld + 3) * 36 + p_ld] = xreg.w;
            {
                float4* ws = (float4*)(s + OFF_W);
                ws[0 * 256 + tid] = wr0; ws[1 * 256 + tid] = wr1;
                ws[2 * 256 + tid] = wr2; ws[3 * 256 + tid] = wr3;
            }
            __syncthreads();
            if (kc < 7) {   // prefetch next chunk while computing
                int k0n = (kc + 1) * 32;
                xreg = *(const float4*)&X[(p0 + p_ld) * FV + k0n + kq_ld];
                const float4* wg = (const float4*)(W1 + k0n * FF);
                wr0 = wg[0 * 256 + tid]; wr1 = wg[1 * 256 + tid];
                wr2 = wg[2 * 256 + tid]; wr3 = wg[3 * 256 + tid];
            }
            #pragma unroll 8
            for (int kk = 0; kk < 32; kk++) {
                float4 xv = *(const float4*)&s[OFF_XT + kk * 36 + pg * 4];
                ulonglong2 wv = *(const ulonglong2*)&s[OFF_W + kk * FF + fg * 4];
                ull a0 = pk2(xv.x, xv.x), a1 = pk2(xv.y, xv.y);
                ull a2 = pk2(xv.z, xv.z), a3 = pk2(xv.w, xv.w);
                accL[0] = fma2(a0, wv.x, accL[0]); accH[0] = fma2(a0, wv.y, accH[0]);
                accL[1] = fma2(a1, wv.x, accL[1]); accH[1] = fma2(a1, wv.y, accH[1]);
                accL[2] = fma2(a2, wv.x, accL[2]); accH[2] = fma2(a2, wv.y, accH[2]);
                accL[3] = fma2(a3, wv.x, accL[3]); accH[3] = fma2(a3, wv.y, accH[3]);
            }
            __syncthreads();
        }
        // write H^T: sHT[f][p]
        #pragma unroll
        for (int i = 0; i < 4; i++) {
            float2 lo = upk(accL[i]), hi = upk(accH[i]);
            int p = pg * 4 + i;
            s[OFF_HT + (fg * 4 + 0) * 36 + p] = lo.x;
            s[OFF_HT + (fg * 4 + 1) * 36 + p] = lo.y;
            s[OFF_HT + (fg * 4 + 2) * 36 + p] = hi.x;
            s[OFF_HT + (fg * 4 + 3) * 36 + p] = hi.y;
        }
        __syncthreads();

        // ---- LayerNorm + ReLU, in place on sHT (warp handles 4 points) ----
        {
            float g0 = lng[lane], g1 = lng[lane + 32], g2 = lng[lane + 64], g3 = lng[lane + 96];
            float c0 = lnb[lane], c1 = lnb[lane + 32], c2 = lnb[lane + 64], c3 = lnb[lane + 96];
            #pragma unroll
            for (int pp = 0; pp < 4; pp++) {
                int p = warp * 4 + pp;
                float v0 = s[OFF_HT + lane * 36 + p];
                float v1 = s[OFF_HT + (lane + 32) * 36 + p];
                float v2 = s[OFF_HT + (lane + 64) * 36 + p];
                float v3 = s[OFF_HT + (lane + 96) * 36 + p];
                float sm = v0 + v1 + v2 + v3;
                #pragma unroll
                for (int o = 16; o; o >>= 1) sm += __shfl_xor_sync(~0u, sm, o);
                float mean = sm * (1.f / FF);
                float d0 = v0 - mean, d1 = v1 - mean, d2 = v2 - mean, d3 = v3 - mean;
                float q = d0 * d0 + d1 * d1 + d2 * d2 + d3 * d3;
                #pragma unroll
                for (int o = 16; o; o >>= 1) q += __shfl_xor_sync(~0u, q, o);
                float inv = rsqrtf(q * (1.f / FF) + 1e-5f);
                s[OFF_HT + lane * 36 + p]        = fmaxf(fmaf(d0 * inv, g0, c0), 0.f);
                s[OFF_HT + (lane + 32) * 36 + p] = fmaxf(fmaf(d1 * inv, g1, c1), 0.f);
                s[OFF_HT + (lane + 64) * 36 + p] = fmaxf(fmaf(d2 * inv, g2, c2), 0.f);
                s[OFF_HT + (lane + 96) * 36 + p] = fmaxf(fmaf(d3 * inv, g3, c3), 0.f);
            }
        }

        // ---- GEMM2: O = relu(H) @ W2 + b2 (prefetched staging) ----
        float4 b2v = ((const float4*)b2)[fg];
        ull oL[4], oH[4];
        #pragma unroll
        for (int i = 0; i < 4; i++) { oL[i] = pk2(b2v.x, b2v.y); oH[i] = pk2(b2v.z, b2v.w); }
        wr0 = ((const float4*)W2)[0 * 256 + tid];
        wr1 = ((const float4*)W2)[1 * 256 + tid];
        wr2 = ((const float4*)W2)[2 * 256 + tid];
        wr3 = ((const float4*)W2)[3 * 256 + tid];
        for (int kc = 0; kc < 4; kc++) {
            int k0 = kc * 32;
            {
                float4* ws = (float4*)(s + OFF_W);
                ws[0 * 256 + tid] = wr0; ws[1 * 256 + tid] = wr1;
                ws[2 * 256 + tid] = wr2; ws[3 * 256 + tid] = wr3;
            }
            __syncthreads();
            if (kc < 3) {
                const float4* wg = (const float4*)(W2 + (k0 + 32) * FF);
                wr0 = wg[0 * 256 + tid]; wr1 = wg[1 * 256 + tid];
                wr2 = wg[2 * 256 + tid]; wr3 = wg[3 * 256 + tid];
            }
            #pragma unroll 8
            for (int kk = 0; kk < 32; kk++) {
                float4 xv = *(const float4*)&s[OFF_HT + (k0 + kk) * 36 + pg * 4];
                ulonglong2 wv = *(const ulonglong2*)&s[OFF_W + kk * FF + fg * 4];
                ull a0 = pk2(xv.x, xv.x), a1 = pk2(xv.y, xv.y);
                ull a2 = pk2(xv.z, xv.z), a3 = pk2(xv.w, xv.w);
                oL[0] = fma2(a0, wv.x, oL[0]); oH[0] = fma2(a0, wv.y, oH[0]);
                oL[1] = fma2(a1, wv.x, oL[1]); oH[1] = fma2(a1, wv.y, oH[1]);
                oL[2] = fma2(a2, wv.x, oL[2]); oH[2] = fma2(a2, wv.y, oH[2]);
                oL[3] = fma2(a3, wv.x, oL[3]); oH[3] = fma2(a3, wv.y, oH[3]);
            }
            __syncthreads();
        }

        // ---- epilogue: store g_feats + O tile, wait for lang, atten -------
        int b = p0 >> 10;
        #pragma unroll
        for (int i = 0; i < 4; i++) {
            float2 lo = upk(oL[i]), hi = upk(oH[i]);
            float4 ov = make_float4(lo.x, lo.y, hi.x, hi.y);
            int p = pg * 4 + i;
            ((float4*)&g_feats[(p0 + p) * FF])[fg] = ov;
            *(float4*)&s[OFF_O + p * 132 + fg * 4] = ov;
        }
        if (tid == 0) { while (atomicAdd(&g_c2, 0) < 64) __nanosleep(64); }
        __syncthreads();
        __threadfence();
        {   // stage lang[b]: 2048 floats
            const float4* lg = (const float4*)(g_lang + b * LL * FF);
            float4* ls = (float4*)(s + OFF_LG);
            ls[tid] = lg[tid];
            ls[tid + 256] = lg[tid + 256];
        }
        __syncthreads();
        #pragma unroll
        for (int pp = 0; pp < 4; pp++) {
            int p = warp * 4 + pp;
            float4 ov = *(const float4*)&s[OFF_O + p * 132 + lane * 4];
            #pragma unroll
            for (int l = 0; l < LL; l++) {
                float4 lv = *(const float4*)&s[OFF_LG + l * FF + lane * 4];
                float d = ov.x * lv.x + ov.y * lv.y + ov.z * lv.z + ov.w * lv.w;
                #pragma unroll
                for (int o = 16; o; o >>= 1) d += __shfl_xor_sync(~0u, d, o);
                if (lane == 0) g_atten[(p0 + p) * LL + l] = d;
            }
        }
    } else {
        // ======================= batched kNN ===============================
        int kb = bid - 192;               // 0..511
        int bq = kb >> 7;                 // batch (128 blocks per batch)
        int lq = (kb & 127) * 8 + warp;   // local query id
        int q  = bq * NPER + lq;          // global query id

        float4* s_p = (float4*)s;         // [1024] packed xyz
        for (int t = tid; t < NPER; t += 256) {
            int g = (bq * NPER + t) * 3;
            s_p[t] = make_float4(xyz[g], xyz[g + 1], xyz[g + 2], 0.f);
        }
        __syncthreads();

        float4 qp = s_p[lq];
        float d[32];
        #pragma unroll
        for (int m = 0; m < 32; m++) {
            float4 p = s_p[m * 32 + lane];   // conflict-free, index-ordered
            float dx = qp.x - p.x, dy = qp.y - p.y, dz = qp.z - p.z;
            d[m] = fmaf(dx, dx, fmaf(dy, dy, dz * dz));
        }

        unsigned sel = 0u;
        for (int r = 0; r < KNN; r++) {
            float mv = 3.4e38f; int mm = 0;
            #pragma unroll
            for (int m = 0; m < 32; m++) {
                bool ok = !((sel >> m) & 1u) && (d[m] < mv);
                if (ok) { mv = d[m]; mm = m; }
            }
            int gi = mm * 32 + lane;
            #pragma unroll
            for (int o = 16; o; o >>= 1) {
                float ov = __shfl_xor_sync(0xffffffffu, mv, o);
                int   oi = __shfl_xor_sync(0xffffffffu, gi, o);
                if (ov < mv || (ov == mv && oi < gi)) { mv = ov; gi = oi; }
            }
            if ((gi & 31) == lane) sel |= 1u << (gi >> 5);
            if (lane == 0) g_knn[q * KNN + r] = bq * NPER + gi;
        }
    }
}

// ---------------- kernel 4: edges, 2 points/block, (4j x 4f) micro-tiles -----
// Two independent 128-thread halves; each half syncs via its own named barrier.
#define NB() asm volatile("bar.sync %0, 128;" :: "r"(half + 1) : "memory")

__global__ __launch_bounds__(256) void k_edge(
    const float* __restrict__ xyz,
    const float* __restrict__ mask,
    const float* __restrict__ Wr1, const float* __restrict__ br1,
    const float* __restrict__ Wr2, const float* __restrict__ br2,
    float* __restrict__ out)
{
    int half = threadIdx.x >> 7;            // 0 or 1
    int tid  = threadIdx.x & 127;
    int i    = blockIdx.x * 2 + half;       // point id
    __shared__ int s_nb[2][KNN];
    __shared__ __align__(16) float s_aT[2][LL][16];     // [l][j] attention
    __shared__ __align__(16) float s_hidT[2][64][20];   // [h][j] rel hidden (pad 20)
    __shared__ __align__(16) float s_geo[2][KNN][12];   // geo, float4-padded rows

    // fold the barrier-counter reset for the NEXT replay (k_mega already done)
    if (blockIdx.x == 0 && threadIdx.x == 255) { g_c1 = 0; g_c2 = 0; }

    if (tid < KNN) s_nb[half][tid] = g_knn[i * KNN + tid];
    NB();

    {   // load neighbor logits transposed: 256 values, 2 per thread
        int j = tid >> 4, l = tid & 15;
        s_aT[half][l][j]     = g_atten[s_nb[half][j] * LL + l];
        s_aT[half][l][j + 8] = g_atten[s_nb[half][j + 8] * LL + l];
    }
    NB();

    // phase A: per-l softmax over the 16 neighbors, * mask[i,l]
    if (tid < LL) {
        int l = tid;
        float m = -3.4e38f;
        #pragma unroll
        for (int j = 0; j < KNN; j++) m = fmaxf(m, s_aT[half][l][j]);
        float e[KNN]; float sum = 0.f;
        #pragma unroll
        for (int j = 0; j < KNN; j++) { e[j] = __expf(s_aT[half][l][j] - m); sum += e[j]; }
        float scale = __fdividef(mask[i * LL + l], sum);
        #pragma unroll
        for (int j = 0; j < KNN; j++) s_aT[half][l][j] = e[j] * scale;
    }
    NB();

    // phase B: per-edge renormalization over l + geometric features
    if (tid < KNN) {
        int j = tid;
        float ssum = 0.f;
        #pragma unroll
        for (int l = 0; l < LL; l++) ssum += s_aT[half][l][j];
        float inv = __fdividef(1.f, ssum + 1e-7f);
        #pragma unroll
        for (int l = 0; l < LL; l++) s_aT[half][l][j] *= inv;

        int nj = s_nb[half][j];
        float xi0 = xyz[i * 3], xi1 = xyz[i * 3 + 1], xi2 = xyz[i * 3 + 2];
        float xj0 = xyz[nj * 3], xj1 = xyz[nj * 3 + 1], xj2 = xyz[nj * 3 + 2];
        float d0 = xi0 - xj0, d1 = xi1 - xj1, d2 = xi2 - xj2;
        float nr = sqrtf(d0 * d0 + d1 * d1 + d2 * d2 + 1e-12f);
        s_geo[half][j][0] = xi0; s_geo[half][j][1] = xi1; s_geo[half][j][2] = xi2;
        s_geo[half][j][3] = xj0; s_geo[half][j][4] = xj1; s_geo[half][j][5] = xj2;
        s_geo[half][j][6] = d0;  s_geo[half][j][7] = d1;  s_geo[half][j][8] = d2;
        s_geo[half][j][9] = nr;  s_geo[half][j][10] = 0.f; s_geo[half][j][11] = 0.f;
    }
    NB();

    // rel MLP hidden: thread = (hg 0..31 -> 2 h, jq 0..3 -> 4 j), packed f32x2
    {
        int hg = tid >> 2, jq = tid & 3;
        ull wv[10];
        #pragma unroll
        for (int dd = 0; dd < 10; dd++) wv[dd] = *(const ull*)&Wr1[dd * 64 + hg * 2];
        float2 bb = *(const float2*)&br1[hg * 2];
        ull bpk = pk2(bb.x, bb.y);
        float r0[4], r1[4];
        #pragma unroll
        for (int jj = 0; jj < 4; jj++) {
            int j = jq * 4 + jj;
            float4 ga = *(const float4*)&s_geo[half][j][0];
            float4 gb = *(const float4*)&s_geo[half][j][4];
            float2 gc = *(const float2*)&s_geo[half][j][8];
            ull a = bpk;
            a = fma2(pk2(ga.x, ga.x), wv[0], a);
            a = fma2(pk2(ga.y, ga.y), wv[1], a);
            a = fma2(pk2(ga.z, ga.z), wv[2], a);
            a = fma2(pk2(ga.w, ga.w), wv[3], a);
            a = fma2(pk2(gb.x, gb.x), wv[4], a);
            a = fma2(pk2(gb.y, gb.y), wv[5], a);
            a = fma2(pk2(gb.z, gb.z), wv[6], a);
            a = fma2(pk2(gb.w, gb.w), wv[7], a);
            a = fma2(pk2(gc.x, gc.x), wv[8], a);
            a = fma2(pk2(gc.y, gc.y), wv[9], a);
            float2 f2 = upk(a);
            r0[jj] = fmaxf(f2.x, 0.f);
            r1[jj] = fmaxf(f2.y, 0.f);
        }
        *(float4*)&s_hidT[half][hg * 2][jq * 4]     = make_float4(r0[0], r0[1], r0[2], r0[3]);
        *(float4*)&s_hidT[half][hg * 2 + 1][jq * 4] = make_float4(r1[0], r1[1], r1[2], r1[3]);
    }
    NB();

    int jg = tid & 3, fg = tid >> 2;    // 4 j-groups x 32 f-groups

    // ew[4j][4f] = hid @ Wr2 + br2  (packed f32x2)
    float4 b2v = ((const float4*)br2)[fg];
    ull ewL[4], ewH[4];
    #pragma unroll
    for (int jj = 0; jj < 4; jj++) { ewL[jj] = pk2(b2v.x, b2v.y); ewH[jj] = pk2(b2v.z, b2v.w); }
    #pragma unroll 8
    for (int k = 0; k < 64; k++) {
        float4 hv = *(const float4*)&s_hidT[half][k][jg * 4];
        ulonglong2 wv = *(const ulonglong2*)&Wr2[k * FF + fg * 4];
        ull a0 = pk2(hv.x, hv.x), a1 = pk2(hv.y, hv.y);
        ull a2 = pk2(hv.z, hv.z), a3 = pk2(hv.w, hv.w);
        ewL[0] = fma2(a0, wv.x, ewL[0]); ewH[0] = fma2(a0, wv.y, ewH[0]);
        ewL[1] = fma2(a1, wv.x, ewL[1]); ewH[1] = fma2(a1, wv.y, ewH[1]);
        ewL[2] = fma2(a2, wv.x, ewL[2]); ewH[2] = fma2(a2, wv.y, ewH[2]);
        ewL[3] = fma2(a3, wv.x, ewL[3]); ewH[3] = fma2(a3, wv.y, ewH[3]);
    }

    // ctx[4j][4f] = att @ lang_b  (packed f32x2)
    ull cxL[4] = {0ull, 0ull, 0ull, 0ull}, cxH[4] = {0ull, 0ull, 0ull, 0ull};
    const float* lb = g_lang + (i >> 10) * LL * FF;
    #pragma unroll
    for (int l = 0; l < LL; l++) {
        float4 av = *(const float4*)&s_aT[half][l][jg * 4];
        ulonglong2 lv = *(const ulonglong2*)&lb[l * FF + fg * 4];
        ull a0 = pk2(av.x, av.x), a1 = pk2(av.y, av.y);
        ull a2 = pk2(av.z, av.z), a3 = pk2(av.w, av.w);
        cxL[0] = fma2(a0, lv.x, cxL[0]); cxH[0] = fma2(a0, lv.y, cxH[0]);
        cxL[1] = fma2(a1, lv.x, cxL[1]); cxH[1] = fma2(a1, lv.y, cxH[1]);
        cxL[2] = fma2(a2, lv.x, cxL[2]); cxH[2] = fma2(a2, lv.y, cxH[2]);
        cxL[3] = fma2(a3, lv.x, cxL[3]); cxH[3] = fma2(a3, lv.y, cxH[3]);
    }

    // msg = feats[col] * ctx * ew, partial-sum over this thread's 4 j
    float4 res = make_float4(0.f, 0.f, 0.f, 0.f);
    #pragma unroll
    for (int jj = 0; jj < 4; jj++) {
        int nj = s_nb[half][jg * 4 + jj];
        float4 fv = ((const float4*)&g_feats[nj * FF])[fg];
        float2 eL = upk(ewL[jj]), eH = upk(ewH[jj]);
        float2 cL = upk(cxL[jj]), cH = upk(cxH[jj]);
        res.x = fmaf(fv.x * cL.x, eL.x, res.x);
        res.y = fmaf(fv.y * cL.y, eL.y, res.y);
        res.z = fmaf(fv.z * cH.x, eH.x, res.z);
        res.w = fmaf(fv.w * cH.y, eH.y, res.w);
    }
    // reduce the 4 jg-threads sharing this f-quad (xor 1, 2 within 4-group)
    #pragma unroll
    for (int o = 1; o <= 2; o <<= 1) {
        res.x += __shfl_xor_sync(~0u, res.x, o);
        res.y += __shfl_xor_sync(~0u, res.y, o);
        res.z += __shfl_xor_sync(~0u, res.z, o);
        res.w += __shfl_xor_sync(~0u, res.w, o);
    }
    if (jg == 0) {
        float4 rv = ((const float4*)&g_feats[i * FF])[fg];
        res.x += rv.x; res.y += rv.y; res.z += rv.z; res.w += rv.w;
        ((float4*)&out[i * FF])[fg] = res;
    }
}

// ---------------- launch ------------------------------------------------------
extern "C" void kernel_launch(void* const* d_in, const int* in_sizes, int n_in,
                              void* d_out, int out_size)
{
    const float* xyz   = (const float*)d_in[0];
    const float* feats = (const float*)d_in[2];
    const float* lft   = (const float*)d_in[3];
    const float* mask  = (const float*)d_in[4];
    const float* W1    = (const float*)d_in[5];
    const float* b1    = (const float*)d_in[6];
    const float* lng   = (const float*)d_in[7];
    const float* lnb   = (const float*)d_in[8];
    const float* W2    = (const float*)d_in[9];
    const float* b2    = (const float*)d_in[10];
    const float* Wl1   = (const float*)d_in[11];
    const float* bl1   = (const float*)d_in[12];
    const float* bng   = (const float*)d_in[13];
    const float* bnb   = (const float*)d_in[14];
    const float* Wl2   = (const float*)d_in[15];
    const float* bl2   = (const float*)d_in[16];
    const float* Wr1   = (const float*)d_in[17];
    const float* br1   = (const float*)d_in[18];
    const float* Wr2   = (const float*)d_in[19];
    const float* br2   = (const float*)d_in[20];
    float* out = (float*)d_out;

    k_mega<<<704, 256>>>(xyz, feats, W1, b1, lng, lnb, W2, b2,
                         lft, Wl1, bl1, bng, bnb, Wl2, bl2);
    k_edge<<<NPTS / 2, 256>>>(xyz, mask, Wr1, br1, Wr2, br2, out);
}

// round 13
// speedup vs baseline: 1.5813x; 1.0419x over previous
#include <cuda_runtime.h>
#include <math.h>

// Problem constants (fixed by setup_inputs)
#define NPTS  4096
#define BB    4
#define NPER  1024
#define LL    16
#define FV    256
#define FLANG 768
#define FF    128
#define KNN   16

// ---------------- scratch (device globals; no allocations allowed) -----------
__device__ __align__(16) float g_feats[NPTS * FF];   // encoded point features
__device__ __align__(16) float g_hl[BB * LL * FF];   // lang hidden pre-BN
__device__ __align__(16) float g_lang[BB * LL * FF]; // encoded lang features
__device__ __align__(16) float g_atten[NPTS * LL];   // per-point/token logits
__device__ int   g_knn[NPTS * KNN];                  // neighbor ids (global)
__device__ int   g_c1, g_c2;                         // inter-block barrier counters

// ---------------- packed f32x2 helpers (sm_103a FFMA2 pipe) ------------------
typedef unsigned long long ull;
__device__ __forceinline__ ull pk2(float x, float y) {
    ull r; asm("mov.b64 %0, {%1, %2};" : "=l"(r) : "f"(x), "f"(y)); return r;
}
__device__ __forceinline__ ull fma2(ull a, ull b, ull c) {
    ull d; asm("fma.rn.f32x2 %0, %1, %2, %3;" : "=l"(d) : "l"(a), "l"(b), "l"(c));
    return d;
}
__device__ __forceinline__ float2 upk(ull a) {
    float2 f; asm("mov.b64 {%0, %1}, %2;" : "=f"(f.x), "=f"(f.y) : "l"(a)); return f;
}

// ---------------- MEGA kernel: lang | feat+atten | kNN -----------------------
// bids [0,64):    lang pipeline (2 phases, inter-block barrier on g_c1/g_c2)
// bids [64,192):  32 points each, block-tiled feat GEMMs + atten epilogue
// bids [192,704): 8 kNN queries each, warp per query, register top-16
#define OFF_XT 0        // [32][36]  (feat stage A, X^T chunk)
#define OFF_W  1152     // [32][128] (feat stage A/C, W chunk)
#define OFF_HT 5248     // [128][36] (feat stage B/C, H^T)
#define OFF_O  0        // [32][132] (feat stage D, O)         -- overlays XT+W
#define OFF_LG 5248     // [16][128] (feat stage D, lang tile) -- overlays HT
#define SBUF   9856

__global__ __launch_bounds__(256) void k_mega(
    const float* __restrict__ xyz, const float* __restrict__ X,
    const float* __restrict__ W1, const float* __restrict__ b1,
    const float* __restrict__ lng, const float* __restrict__ lnb,
    const float* __restrict__ W2, const float* __restrict__ b2,
    const float* __restrict__ LFT, const float* __restrict__ Wl1,
    const float* __restrict__ bl1, const float* __restrict__ bng,
    const float* __restrict__ bnb, const float* __restrict__ Wl2,
    const float* __restrict__ bl2)
{
    __shared__ __align__(16) float s[SBUF];
    int bid = blockIdx.x, tid = threadIdx.x, lane = tid & 31, warp = tid >> 5;

    if (bid < 64) {
        // ========================= LANG pipeline ===========================
        int r = bid;
        float* s_in = s;                            // 768 floats (also s_h)
        float4* s_part = (float4*)(s + 768);        // [8][32] float4

        // phase 1: hl = LFT @ Wl1 + bl1 (8-way v-split, 256 threads)
        for (int t = tid; t < FLANG; t += 256) s_in[t] = LFT[r * FLANG + t];
        __syncthreads();
        int fq = tid & 31, vs = tid >> 5;
        float4 acc = make_float4(0.f, 0.f, 0.f, 0.f);
        const float4* sv = (const float4*)(s_in + vs * 96);   // 24 float4
        int vbase = vs * 96;
        #pragma unroll 4
        for (int v4 = 0; v4 < 24; v4++) {
            float4 x = sv[v4];
            float4 w0 = ((const float4*)(Wl1 + (vbase + v4 * 4 + 0) * FF))[fq];
            float4 w1 = ((const float4*)(Wl1 + (vbase + v4 * 4 + 1) * FF))[fq];
            float4 w2 = ((const float4*)(Wl1 + (vbase + v4 * 4 + 2) * FF))[fq];
            float4 w3 = ((const float4*)(Wl1 + (vbase + v4 * 4 + 3) * FF))[fq];
            acc.x = fmaf(x.x, w0.x, acc.x); acc.y = fmaf(x.x, w0.y, acc.y);
            acc.z = fmaf(x.x, w0.z, acc.z); acc.w = fmaf(x.x, w0.w, acc.w);
            acc.x = fmaf(x.y, w1.x, acc.x); acc.y = fmaf(x.y, w1.y, acc.y);
            acc.z = fmaf(x.y, w1.z, acc.z); acc.w = fmaf(x.y, w1.w, acc.w);
            acc.x = fmaf(x.z, w2.x, acc.x); acc.y = fmaf(x.z, w2.y, acc.y);
            acc.z = fmaf(x.z, w2.z, acc.z); acc.w = fmaf(x.z, w2.w, acc.w);
            acc.x = fmaf(x.w, w3.x, acc.x); acc.y = fmaf(x.w, w3.y, acc.y);
            acc.z = fmaf(x.w, w3.z, acc.z); acc.w = fmaf(x.w, w3.w, acc.w);
        }
        s_part[vs * 32 + fq] = acc;
        __syncthreads();
        if (tid < 32) {
            float4 o = ((const float4*)bl1)[tid];
            #pragma unroll
            for (int p = 0; p < 8; p++) {
                float4 a = s_part[p * 32 + tid];
                o.x += a.x; o.y += a.y; o.z += a.z; o.w += a.w;
            }
            ((float4*)(g_hl + r * FF))[tid] = o;
            __threadfence();
        }
        __syncthreads();
        if (tid == 0) {
            atomicAdd(&g_c1, 1);
            while (atomicAdd(&g_c1, 0) < 64) __nanosleep(64);
        }
        __syncthreads();
        __threadfence();

        // phase 2: BN (global stats, recomputed redundantly) + ReLU
        if (tid < FF) {
            int f = tid;
            float m = 0.f;
            #pragma unroll 8
            for (int rr = 0; rr < 64; rr++) m += g_hl[rr * FF + f];
            m *= (1.f / 64.f);
            float v = 0.f;
            #pragma unroll 8
            for (int rr = 0; rr < 64; rr++) { float d = g_hl[rr * FF + f] - m; v = fmaf(d, d, v); }
            v *= (1.f / 64.f);
            float h = (g_hl[r * FF + f] - m) * rsqrtf(v + 1e-5f) * bng[f] + bnb[f];
            s_in[f] = fmaxf(h, 0.f);
        }
        __syncthreads();

        // phase 3: lang = relu(h) @ Wl2 + bl2 (8-way c-split)
        float4 acc2 = make_float4(0.f, 0.f, 0.f, 0.f);
        #pragma unroll 8
        for (int c = vs * 16; c < vs * 16 + 16; c++) {
            float x = s_in[c];
            float4 w = ((const float4*)(Wl2 + c * FF))[fq];
            acc2.x = fmaf(x, w.x, acc2.x); acc2.y = fmaf(x, w.y, acc2.y);
            acc2.z = fmaf(x, w.z, acc2.z); acc2.w = fmaf(x, w.w, acc2.w);
        }
        s_part[vs * 32 + fq] = acc2;
        __syncthreads();
        if (tid < 32) {
            float4 o = ((const float4*)bl2)[tid];
            #pragma unroll
            for (int p = 0; p < 8; p++) {
                float4 a = s_part[p * 32 + tid];
                o.x += a.x; o.y += a.y; o.z += a.z; o.w += a.w;
            }
            ((float4*)(g_lang + r * FF))[tid] = o;
            __threadfence();
        }
        __syncthreads();
        if (tid == 0) atomicAdd(&g_c2, 1);

    } else if (bid < 192) {
        // ================= tiled feat encoder + attention ==================
        int p0 = (bid - 64) * 32;
        int pg = tid & 7, fg = tid >> 3;   // 8 point-groups x 32 f-groups
        int p_ld = tid >> 3, kq_ld = (tid & 7) * 4;

        // ---- GEMM1: H = X @ W1 + b1 (packed f32x2, prefetched staging) ----
        float4 bv = ((const float4*)b1)[fg];
        ull accL[4], accH[4];
        #pragma unroll
        for (int i = 0; i < 4; i++) { accL[i] = pk2(bv.x, bv.y); accH[i] = pk2(bv.z, bv.w); }

        // prologue prefetch (chunk 0)
        float4 xreg = *(const float4*)&X[(p0 + p_ld) * FV + kq_ld];
        float4 wr0 = ((const float4*)W1)[0 * 256 + tid];
        float4 wr1 = ((const float4*)W1)[1 * 256 + tid];
        float4 wr2 = ((const float4*)W1)[2 * 256 + tid];
        float4 wr3 = ((const float4*)W1)[3 * 256 + tid];

        for (int kc = 0; kc < 8; kc++) {
            // commit staged chunk
            s[OFF_XT + (kq_ld + 0) * 36 + p_ld] = xreg.x;
            s[OFF_XT + (kq_ld + 1) * 36 + p_ld] = xreg.y;
            s[OFF_XT + (kq_ld + 2) * 36 + p_ld] = xreg.z;
            s[OFF_XT + (kq_ld + 3) * 36 + p_ld] = xreg.w;
            {
                float4* ws = (float4*)(s + OFF_W);
                ws[0 * 256 + tid] = wr0; ws[1 * 256 + tid] = wr1;
                ws[2 * 256 + tid] = wr2; ws[3 * 256 + tid] = wr3;
            }
            __syncthreads();
            if (kc < 7) {   // prefetch next chunk while computing
                int k0n = (kc + 1) * 32;
                xreg = *(const float4*)&X[(p0 + p_ld) * FV + k0n + kq_ld];
                const float4* wg = (const float4*)(W1 + k0n * FF);
                wr0 = wg[0 * 256 + tid]; wr1 = wg[1 * 256 + tid];
                wr2 = wg[2 * 256 + tid]; wr3 = wg[3 * 256 + tid];
            }
            #pragma unroll 8
            for (int kk = 0; kk < 32; kk++) {
                float4 xv = *(const float4*)&s[OFF_XT + kk * 36 + pg * 4];
                ulonglong2 wv = *(const ulonglong2*)&s[OFF_W + kk * FF + fg * 4];
                ull a0 = pk2(xv.x, xv.x), a1 = pk2(xv.y, xv.y);
                ull a2 = pk2(xv.z, xv.z), a3 = pk2(xv.w, xv.w);
                accL[0] = fma2(a0, wv.x, accL[0]); accH[0] = fma2(a0, wv.y, accH[0]);
                accL[1] = fma2(a1, wv.x, accL[1]); accH[1] = fma2(a1, wv.y, accH[1]);
                accL[2] = fma2(a2, wv.x, accL[2]); accH[2] = fma2(a2, wv.y, accH[2]);
                accL[3] = fma2(a3, wv.x, accL[3]); accH[3] = fma2(a3, wv.y, accH[3]);
            }
            __syncthreads();
        }
        // write H^T: sHT[f][p]
        #pragma unroll
        for (int i = 0; i < 4; i++) {
            float2 lo = upk(accL[i]), hi = upk(accH[i]);
            int p = pg * 4 + i;
            s[OFF_HT + (fg * 4 + 0) * 36 + p] = lo.x;
            s[OFF_HT + (fg * 4 + 1) * 36 + p] = lo.y;
            s[OFF_HT + (fg * 4 + 2) * 36 + p] = hi.x;
            s[OFF_HT + (fg * 4 + 3) * 36 + p] = hi.y;
        }
        __syncthreads();

        // ---- LayerNorm + ReLU, in place on sHT (warp handles 4 points) ----
        {
            float g0 = lng[lane], g1 = lng[lane + 32], g2 = lng[lane + 64], g3 = lng[lane + 96];
            float c0 = lnb[lane], c1 = lnb[lane + 32], c2 = lnb[lane + 64], c3 = lnb[lane + 96];
            #pragma unroll
            for (int pp = 0; pp < 4; pp++) {
                int p = warp * 4 + pp;
                float v0 = s[OFF_HT + lane * 36 + p];
                float v1 = s[OFF_HT + (lane + 32) * 36 + p];
                float v2 = s[OFF_HT + (lane + 64) * 36 + p];
                float v3 = s[OFF_HT + (lane + 96) * 36 + p];
                float sm = v0 + v1 + v2 + v3;
                #pragma unroll
                for (int o = 16; o; o >>= 1) sm += __shfl_xor_sync(~0u, sm, o);
                float mean = sm * (1.f / FF);
                float d0 = v0 - mean, d1 = v1 - mean, d2 = v2 - mean, d3 = v3 - mean;
                float q = d0 * d0 + d1 * d1 + d2 * d2 + d3 * d3;
                #pragma unroll
                for (int o = 16; o; o >>= 1) q += __shfl_xor_sync(~0u, q, o);
                float inv = rsqrtf(q * (1.f / FF) + 1e-5f);
                s[OFF_HT + lane * 36 + p]        = fmaxf(fmaf(d0 * inv, g0, c0), 0.f);
                s[OFF_HT + (lane + 32) * 36 + p] = fmaxf(fmaf(d1 * inv, g1, c1), 0.f);
                s[OFF_HT + (lane + 64) * 36 + p] = fmaxf(fmaf(d2 * inv, g2, c2), 0.f);
                s[OFF_HT + (lane + 96) * 36 + p] = fmaxf(fmaf(d3 * inv, g3, c3), 0.f);
            }
        }

        // ---- GEMM2: O = relu(H) @ W2 + b2 (prefetched staging) ----
        float4 b2v = ((const float4*)b2)[fg];
        ull oL[4], oH[4];
        #pragma unroll
        for (int i = 0; i < 4; i++) { oL[i] = pk2(b2v.x, b2v.y); oH[i] = pk2(b2v.z, b2v.w); }
        wr0 = ((const float4*)W2)[0 * 256 + tid];
        wr1 = ((const float4*)W2)[1 * 256 + tid];
        wr2 = ((const float4*)W2)[2 * 256 + tid];
        wr3 = ((const float4*)W2)[3 * 256 + tid];
        for (int kc = 0; kc < 4; kc++) {
            int k0 = kc * 32;
            {
                float4* ws = (float4*)(s + OFF_W);
                ws[0 * 256 + tid] = wr0; ws[1 * 256 + tid] = wr1;
                ws[2 * 256 + tid] = wr2; ws[3 * 256 + tid] = wr3;
            }
            __syncthreads();
            if (kc < 3) {
                const float4* wg = (const float4*)(W2 + (k0 + 32) * FF);
                wr0 = wg[0 * 256 + tid]; wr1 = wg[1 * 256 + tid];
                wr2 = wg[2 * 256 + tid]; wr3 = wg[3 * 256 + tid];
            }
            #pragma unroll 8
            for (int kk = 0; kk < 32; kk++) {
                float4 xv = *(const float4*)&s[OFF_HT + (k0 + kk) * 36 + pg * 4];
                ulonglong2 wv = *(const ulonglong2*)&s[OFF_W + kk * FF + fg * 4];
                ull a0 = pk2(xv.x, xv.x), a1 = pk2(xv.y, xv.y);
                ull a2 = pk2(xv.z, xv.z), a3 = pk2(xv.w, xv.w);
                oL[0] = fma2(a0, wv.x, oL[0]); oH[0] = fma2(a0, wv.y, oH[0]);
                oL[1] = fma2(a1, wv.x, oL[1]); oH[1] = fma2(a1, wv.y, oH[1]);
                oL[2] = fma2(a2, wv.x, oL[2]); oH[2] = fma2(a2, wv.y, oH[2]);
                oL[3] = fma2(a3, wv.x, oL[3]); oH[3] = fma2(a3, wv.y, oH[3]);
            }
            __syncthreads();
        }

        // ---- epilogue: store g_feats + O tile, wait for lang, atten -------
        int b = p0 >> 10;
        #pragma unroll
        for (int i = 0; i < 4; i++) {
            float2 lo = upk(oL[i]), hi = upk(oH[i]);
            float4 ov = make_float4(lo.x, lo.y, hi.x, hi.y);
            int p = pg * 4 + i;
            ((float4*)&g_feats[(p0 + p) * FF])[fg] = ov;
            *(float4*)&s[OFF_O + p * 132 + fg * 4] = ov;
        }
        if (tid == 0) { while (atomicAdd(&g_c2, 0) < 64) __nanosleep(64); }
        __syncthreads();
        __threadfence();
        {   // stage lang[b]: 2048 floats
            const float4* lg = (const float4*)(g_lang + b * LL * FF);
            float4* ls = (float4*)(s + OFF_LG);
            ls[tid] = lg[tid];
            ls[tid + 256] = lg[tid + 256];
        }
        __syncthreads();
        #pragma unroll
        for (int pp = 0; pp < 4; pp++) {
            int p = warp * 4 + pp;
            float4 ov = *(const float4*)&s[OFF_O + p * 132 + lane * 4];
            #pragma unroll
            for (int l = 0; l < LL; l++) {
                float4 lv = *(const float4*)&s[OFF_LG + l * FF + lane * 4];
                float d = ov.x * lv.x + ov.y * lv.y + ov.z * lv.z + ov.w * lv.w;
                #pragma unroll
                for (int o = 16; o; o >>= 1) d += __shfl_xor_sync(~0u, d, o);
                if (lane == 0) g_atten[(p0 + p) * LL + l] = d;
            }
        }
    } else {
        // ======================= batched kNN ===============================
        int kb = bid - 192;               // 0..511
        int bq = kb >> 7;                 // batch (128 blocks per batch)
        int lq = (kb & 127) * 8 + warp;   // local query id
        int q  = bq * NPER + lq;          // global query id

        float4* s_p = (float4*)s;         // [1024] packed xyz
        for (int t = tid; t < NPER; t += 256) {
            int g = (bq * NPER + t) * 3;
            s_p[t] = make_float4(xyz[g], xyz[g + 1], xyz[g + 2], 0.f);
        }
        __syncthreads();

        float4 qp = s_p[lq];
        float d[32];
        #pragma unroll
        for (int m = 0; m < 32; m++) {
            float4 p = s_p[m * 32 + lane];   // conflict-free, index-ordered
            float dx = qp.x - p.x, dy = qp.y - p.y, dz = qp.z - p.z;
            d[m] = fmaf(dx, dx, fmaf(dy, dy, dz * dz));
        }

        unsigned sel = 0u;
        for (int r = 0; r < KNN; r++) {
            float mv = 3.4e38f; int mm = 0;
            #pragma unroll
            for (int m = 0; m < 32; m++) {
                bool ok = !((sel >> m) & 1u) && (d[m] < mv);
                if (ok) { mv = d[m]; mm = m; }
            }
            int gi = mm * 32 + lane;
            #pragma unroll
            for (int o = 16; o; o >>= 1) {
                float ov = __shfl_xor_sync(0xffffffffu, mv, o);
                int   oi = __shfl_xor_sync(0xffffffffu, gi, o);
                if (ov < mv || (ov == mv && oi < gi)) { mv = ov; gi = oi; }
            }
            if ((gi & 31) == lane) sel |= 1u << (gi >> 5);
            if (lane == 0) g_knn[q * KNN + r] = bq * NPER + gi;
        }
    }
}

// ---------------- kernel 4: edges, 2 pts/block, dual-track overlapped prep ---
// Per half (128 thr): warps 0-1 = softmax track, warps 2-3 = geo+hidden track.
// Named barriers: 1,2 = per-half full (128); 3,4 = softmax-track (64);
//                 5,6 = hidden-track (64).
#define NB() asm volatile("bar.sync %0, 128;" :: "r"(half + 1) : "memory")

__global__ __launch_bounds__(256) void k_edge(
    const float* __restrict__ xyz,
    const float* __restrict__ mask,
    const float* __restrict__ Wr1, const float* __restrict__ br1,
    const float* __restrict__ Wr2, const float* __restrict__ br2,
    float* __restrict__ out)
{
    int half = threadIdx.x >> 7;            // 0 or 1
    int tid  = threadIdx.x & 127;
    int i    = blockIdx.x * 2 + half;       // point id
    __shared__ int s_nb[2][KNN];
    __shared__ __align__(16) float s_aT[2][LL][16];     // [l][j] attention
    __shared__ __align__(16) float s_hidT[2][64][20];   // [h][j] rel hidden (pad 20)
    __shared__ __align__(16) float s_geo[2][KNN][12];   // geo, float4-padded rows

    // fold the barrier-counter reset for the NEXT replay (k_mega already done)
    if (blockIdx.x == 0 && threadIdx.x == 255) { g_c1 = 0; g_c2 = 0; }

    if (tid < KNN) s_nb[half][tid] = g_knn[i * KNN + tid];
    NB();

    if (tid < 64) {
        // ============== softmax track (warps 0-1 of this half) =============
        {   // load neighbor logits transposed: 4 per thread
            int l = tid & 15, j0 = tid >> 4;        // j0 in [0,4)
            #pragma unroll
            for (int jj = 0; jj < 4; jj++) {
                int j = j0 + jj * 4;
                s_aT[half][l][j] = g_atten[s_nb[half][j] * LL + l];
            }
        }
        asm volatile("bar.sync %0, 64;" :: "r"(3 + half) : "memory");

        // phase A: per-l softmax over the 16 neighbors, * mask[i,l]
        if (tid < LL) {
            int l = tid;
            float m = -3.4e38f;
            #pragma unroll
            for (int j = 0; j < KNN; j++) m = fmaxf(m, s_aT[half][l][j]);
            float e[KNN]; float sum = 0.f;
            #pragma unroll
            for (int j = 0; j < KNN; j++) { e[j] = __expf(s_aT[half][l][j] - m); sum += e[j]; }
            float scale = __fdividef(mask[i * LL + l], sum);
            #pragma unroll
            for (int j = 0; j < KNN; j++) s_aT[half][l][j] = e[j] * scale;
        }
        __syncwarp();

        // phase B: per-edge renormalization over l (same warp as phase A)
        if (tid < KNN) {
            int j = tid;
            float ssum = 0.f;
            #pragma unroll
            for (int l = 0; l < LL; l++) ssum += s_aT[half][l][j];
            float inv = __fdividef(1.f, ssum + 1e-7f);
            #pragma unroll
            for (int l = 0; l < LL; l++) s_aT[half][l][j] *= inv;
        }
    } else {
        // ============= geo + hidden track (warps 2-3 of this half) =========
        int t2 = tid - 64;                   // [0,64)
        {   // prefetch the 16 neighbor feats rows into L1 (64 lines, 1/thread)
            int j = t2 >> 2, ln = t2 & 3;
            const float* pf = &g_feats[s_nb[half][j] * FF + ln * 32];
            asm volatile("prefetch.global.L1 [%0];" :: "l"(pf));
        }
        if (t2 < KNN) {                      // geometric edge features
            int j = t2, nj = s_nb[half][j];
            float xi0 = xyz[i * 3], xi1 = xyz[i * 3 + 1], xi2 = xyz[i * 3 + 2];
            float xj0 = xyz[nj * 3], xj1 = xyz[nj * 3 + 1], xj2 = xyz[nj * 3 + 2];
            float d0 = xi0 - xj0, d1 = xi1 - xj1, d2 = xi2 - xj2;
            float nr = sqrtf(d0 * d0 + d1 * d1 + d2 * d2 + 1e-12f);
            s_geo[half][j][0] = xi0; s_geo[half][j][1] = xi1; s_geo[half][j][2] = xi2;
            s_geo[half][j][3] = xj0; s_geo[half][j][4] = xj1; s_geo[half][j][5] = xj2;
            s_geo[half][j][6] = d0;  s_geo[half][j][7] = d1;  s_geo[half][j][8] = d2;
            s_geo[half][j][9] = nr;  s_geo[half][j][10] = 0.f; s_geo[half][j][11] = 0.f;
        }
        asm volatile("bar.sync %0, 64;" :: "r"(5 + half) : "memory");

        // rel MLP hidden (64 threads): hp = 2 h, jq = 8 j, packed f32x2
        int hp = t2 & 31, jq = t2 >> 5;
        ull wv[10];
        #pragma unroll
        for (int dd = 0; dd < 10; dd++) wv[dd] = *(const ull*)&Wr1[dd * 64 + hp * 2];
        float2 bb = *(const float2*)&br1[hp * 2];
        ull bpk = pk2(bb.x, bb.y);
        float r0[8], r1[8];
        #pragma unroll
        for (int jj = 0; jj < 8; jj++) {
            int j = jq * 8 + jj;
            float4 ga = *(const float4*)&s_geo[half][j][0];
            float4 gb = *(const float4*)&s_geo[half][j][4];
            float2 gc = *(const float2*)&s_geo[half][j][8];
            ull a = bpk;
            a = fma2(pk2(ga.x, ga.x), wv[0], a);
            a = fma2(pk2(ga.y, ga.y), wv[1], a);
            a = fma2(pk2(ga.z, ga.z), wv[2], a);
            a = fma2(pk2(ga.w, ga.w), wv[3], a);
            a = fma2(pk2(gb.x, gb.x), wv[4], a);
            a = fma2(pk2(gb.y, gb.y), wv[5], a);
            a = fma2(pk2(gb.z, gb.z), wv[6], a);
            a = fma2(pk2(gb.w, gb.w), wv[7], a);
            a = fma2(pk2(gc.x, gc.x), wv[8], a);
            a = fma2(pk2(gc.y, gc.y), wv[9], a);
            float2 f2 = upk(a);
            r0[jj] = fmaxf(f2.x, 0.f);
            r1[jj] = fmaxf(f2.y, 0.f);
        }
        *(float4*)&s_hidT[half][hp * 2][jq * 8]         = make_float4(r0[0], r0[1], r0[2], r0[3]);
        *(float4*)&s_hidT[half][hp * 2][jq * 8 + 4]     = make_float4(r0[4], r0[5], r0[6], r0[7]);
        *(float4*)&s_hidT[half][hp * 2 + 1][jq * 8]     = make_float4(r1[0], r1[1], r1[2], r1[3]);
        *(float4*)&s_hidT[half][hp * 2 + 1][jq * 8 + 4] = make_float4(r1[4], r1[5], r1[6], r1[7]);
    }
    NB();   // join both tracks before the GEMM phase

    int jg = tid & 3, fg = tid >> 2;    // 4 j-groups x 32 f-groups

    // ew[4j][4f] = hid @ Wr2 + br2  (packed f32x2)
    float4 b2v = ((const float4*)br2)[fg];
    ull ewL[4], ewH[4];
    #pragma unroll
    for (int jj = 0; jj < 4; jj++) { ewL[jj] = pk2(b2v.x, b2v.y); ewH[jj] = pk2(b2v.z, b2v.w); }
    #pragma unroll 8
    for (int k = 0; k < 64; k++) {
        float4 hv = *(const float4*)&s_hidT[half][k][jg * 4];
        ulonglong2 wv = *(const ulonglong2*)&Wr2[k * FF + fg * 4];
        ull a0 = pk2(hv.x, hv.x), a1 = pk2(hv.y, hv.y);
        ull a2 = pk2(hv.z, hv.z), a3 = pk2(hv.w, hv.w);
        ewL[0] = fma2(a0, wv.x, ewL[0]); ewH[0] = fma2(a0, wv.y, ewH[0]);
        ewL[1] = fma2(a1, wv.x, ewL[1]); ewH[1] = fma2(a1, wv.y, ewH[1]);
        ewL[2] = fma2(a2, wv.x, ewL[2]); ewH[2] = fma2(a2, wv.y, ewH[2]);
        ewL[3] = fma2(a3, wv.x, ewL[3]); ewH[3] = fma2(a3, wv.y, ewH[3]);
    }

    // ctx[4j][4f] = att @ lang_b  (packed f32x2)
    ull cxL[4] = {0ull, 0ull, 0ull, 0ull}, cxH[4] = {0ull, 0ull, 0ull, 0ull};
    const float* lb = g_lang + (i >> 10) * LL * FF;
    #pragma unroll
    for (int l = 0; l < LL; l++) {
        float4 av = *(const float4*)&s_aT[half][l][jg * 4];
        ulonglong2 lv = *(const ulonglong2*)&lb[l * FF + fg * 4];
        ull a0 = pk2(av.x, av.x), a1 = pk2(av.y, av.y);
        ull a2 = pk2(av.z, av.z), a3 = pk2(av.w, av.w);
        cxL[0] = fma2(a0, lv.x, cxL[0]); cxH[0] = fma2(a0, lv.y, cxH[0]);
        cxL[1] = fma2(a1, lv.x, cxL[1]); cxH[1] = fma2(a1, lv.y, cxH[1]);
        cxL[2] = fma2(a2, lv.x, cxL[2]); cxH[2] = fma2(a2, lv.y, cxH[2]);
        cxL[3] = fma2(a3, lv.x, cxL[3]); cxH[3] = fma2(a3, lv.y, cxH[3]);
    }

    // msg = feats[col] * ctx * ew, partial-sum over this thread's 4 j
    float4 res = make_float4(0.f, 0.f, 0.f, 0.f);
    #pragma unroll
    for (int jj = 0; jj < 4; jj++) {
        int nj = s_nb[half][jg * 4 + jj];
        float4 fv = ((const float4*)&g_feats[nj * FF])[fg];
        float2 eL = upk(ewL[jj]), eH = upk(ewH[jj]);
        float2 cL = upk(cxL[jj]), cH = upk(cxH[jj]);
        res.x = fmaf(fv.x * cL.x, eL.x, res.x);
        res.y = fmaf(fv.y * cL.y, eL.y, res.y);
        res.z = fmaf(fv.z * cH.x, eH.x, res.z);
        res.w = fmaf(fv.w * cH.y, eH.y, res.w);
    }
    // reduce the 4 jg-threads sharing this f-quad (xor 1, 2 within 4-group)
    #pragma unroll
    for (int o = 1; o <= 2; o <<= 1) {
        res.x += __shfl_xor_sync(~0u, res.x, o);
        res.y += __shfl_xor_sync(~0u, res.y, o);
        res.z += __shfl_xor_sync(~0u, res.z, o);
        res.w += __shfl_xor_sync(~0u, res.w, o);
    }
    if (jg == 0) {
        float4 rv = ((const float4*)&g_feats[i * FF])[fg];
        res.x += rv.x; res.y += rv.y; res.z += rv.z; res.w += rv.w;
        ((float4*)&out[i * FF])[fg] = res;
    }
}

// ---------------- launch ------------------------------------------------------
extern "C" void kernel_launch(void* const* d_in, const int* in_sizes, int n_in,
                              void* d_out, int out_size)
{
    const float* xyz   = (const float*)d_in[0];
    const float* feats = (const float*)d_in[2];
    const float* lft   = (const float*)d_in[3];
    const float* mask  = (const float*)d_in[4];
    const float* W1    = (const float*)d_in[5];
    const float* b1    = (const float*)d_in[6];
    const float* lng   = (const float*)d_in[7];
    const float* lnb   = (const float*)d_in[8];
    const float* W2    = (const float*)d_in[9];
    const float* b2    = (const float*)d_in[10];
    const float* Wl1   = (const float*)d_in[11];
    const float* bl1   = (const float*)d_in[12];
    const float* bng   = (const float*)d_in[13];
    const float* bnb   = (const float*)d_in[14];
    const float* Wl2   = (const float*)d_in[15];
    const float* bl2   = (const float*)d_in[16];
    const float* Wr1   = (const float*)d_in[17];
    const float* br1   = (const float*)d_in[18];
    const float* Wr2   = (const float*)d_in[19];
    const float* br2   = (const float*)d_in[20];
    float* out = (float*)d_out;

    k_mega<<<704, 256>>>(xyz, feats, W1, b1, lng, lnb, W2, b2,
                         lft, Wl1, bl1, bng, bnb, Wl2, bl2);
    k_edge<<<NPTS / 2, 256>>>(xyz, mask, Wr1, br1, Wr2, br2, out);
}